// round 11
// baseline (speedup 1.0000x reference)
#include <cuda_runtime.h>
#include <cstdint>
#include <cstddef>

// Problem constants
#define Bc 256
#define Dc 256
#define Kc 1024
#define Ec 16
#define KSPLIT 8
#define KH (Kc / KSPLIT)   // 128 codes per argmin block

// Output offsets (floats) within d_out, in reference return order:
// cw_embed (B, D*E), one_hot (B, D, K), new_codebook (D, K, E), new_ema (D, K)
static const size_t OFF_EMB = 0;
static const size_t OFF_OH  = (size_t)Bc * Dc * Ec;                    // 1,048,576
static const size_t OFF_NCB = OFF_OH + (size_t)Bc * Dc * Kc;           // 68,157,440
static const size_t OFF_NEC = OFF_NCB + (size_t)Dc * Kc * Ec;          // 72,351,744

// One_hot zero-fill: 67,108,864 floats / 2048 blocks = 32768 floats per block.
#define ZCHUNK 32768

// Scratch: packed argmin keys (non-atomic, owner-written)
__device__ unsigned long long g_key[KSPLIT * Dc * Bc];

// ---- packed f32x2 helpers (Blackwell) ----
__device__ __forceinline__ unsigned long long pk2(float a, float b) {
    unsigned long long r;
    asm("mov.b64 %0,{%1,%2};" : "=l"(r) : "f"(a), "f"(b));
    return r;
}
__device__ __forceinline__ void upk2(unsigned long long v, float& a, float& b) {
    asm("mov.b64 {%0,%1},%2;" : "=f"(a), "=f"(b) : "l"(v));
}
__device__ __forceinline__ unsigned long long f2fma(unsigned long long a, unsigned long long b, unsigned long long c) {
    unsigned long long d;
    asm("fma.rn.f32x2 %0,%1,%2,%3;" : "=l"(d) : "l"(a), "l"(b), "l"(c));
    return d;
}
__device__ __forceinline__ unsigned long long f2add(unsigned long long a, unsigned long long b) {
    unsigned long long d;
    asm("add.rn.f32x2 %0,%1,%2;" : "=l"(d) : "l"(a), "l"(b));
    return d;
}

// Map float to an order-preserving uint (no NaNs expected).
__device__ __forceinline__ unsigned int orderable(float f) {
    unsigned int u = __float_as_uint(f);
    return (u & 0x80000000u) ? ~u : (u | 0x80000000u);
}

// =====================================================================
// Kernel 1: argmin over one K-chunk + one_hot zero-fill.
// grid = (Dc, KSPLIT), block = 64. Thread t handles batches t+64r, r=0..3.
// Zero stores paced: 2 STG.128 per k-pair iteration (smooth DRAM issue).
// =====================================================================
__global__ void __launch_bounds__(64, 4)
vq_argmin_zf(const float* __restrict__ cw_q,
             const float* __restrict__ codebook,
             float* __restrict__ out)
{
    // cpack[(k>>1)*32 + e*2 + (k&1)] = codebook[d][sp*KH + k][e]
    __shared__ float cpack[KH * Ec];         // 8 KB
    __shared__ float c2f[KH];                // 0.5 KB (code pairs adjacent)

    const int d  = blockIdx.x;
    const int sp = blockIdx.y;
    const int t  = threadIdx.x;
    const float* cb = codebook + ((size_t)d * Kc + (size_t)sp * KH) * Ec;

    // stage + pack codebook chunk (512 float4s, 8 per thread)
    #pragma unroll
    for (int i = t; i < (KH * Ec) / 4; i += 64) {
        float4 v = ((const float4*)cb)[i];
        int k  = i >> 2;
        int e0 = (i & 3) * 4;
        float* dstp = &cpack[(k >> 1) * 32 + (k & 1)];
        dstp[(e0 + 0) * 2] = v.x;
        dstp[(e0 + 1) * 2] = v.y;
        dstp[(e0 + 2) * 2] = v.z;
        dstp[(e0 + 3) * 2] = v.w;
    }
    __syncthreads();

    // per-k squared norms (2 per thread)
    #pragma unroll
    for (int k = t; k < KH; k += 64) {
        const float* cp = cpack + (k >> 1) * 32 + (k & 1);
        float s = 0.f;
        #pragma unroll
        for (int e = 0; e < 16; e++) { float c = cp[e * 2]; s += c * c; }
        c2f[k] = s;
    }
    __syncthreads();

    // load x for 4 batches; pack (-2x) duplicates (exactly -2 * original chain)
    unsigned long long xx[4][16];
    unsigned long long X2[4];
    #pragma unroll
    for (int r = 0; r < 4; r++) {
        const float* xp = cw_q + (size_t)(t + 64 * r) * (Dc * Ec) + (size_t)d * Ec;
        float x2 = 0.f;
        #pragma unroll
        for (int q = 0; q < 4; q++) {
            float4 v = ((const float4*)xp)[q];
            x2 += v.x * v.x; x2 += v.y * v.y; x2 += v.z * v.z; x2 += v.w * v.w;
            xx[r][4*q+0] = pk2(-2.0f*v.x, -2.0f*v.x);
            xx[r][4*q+1] = pk2(-2.0f*v.y, -2.0f*v.y);
            xx[r][4*q+2] = pk2(-2.0f*v.z, -2.0f*v.z);
            xx[r][4*q+3] = pk2(-2.0f*v.w, -2.0f*v.w);
        }
        X2[r] = pk2(x2, x2);
    }

    const unsigned long long ZZ = pk2(0.0f, 0.0f);
    const unsigned long long* c2p = (const unsigned long long*)c2f;
    const ulonglong2* cp2 = (const ulonglong2*)cpack;

    float best[4] = {3.4e38f, 3.4e38f, 3.4e38f, 3.4e38f};
    int   bi[4]   = {0, 0, 0, 0};

    float4* z4 = (float4*)(out + OFF_OH + (size_t)(d * KSPLIT + sp) * ZCHUNK);
    const float4 zf4 = make_float4(0.f, 0.f, 0.f, 0.f);

    // 64 k-pairs; 2 paced zero-stores per pair = 128 float4/thread total
    #pragma unroll 1
    for (int p = 0; p < KH / 2; p++) {
        const ulonglong2* row = cp2 + p * 8;
        unsigned long long acc[4][4];
        #pragma unroll
        for (int r = 0; r < 4; r++) {
            acc[r][0] = ZZ; acc[r][1] = ZZ; acc[r][2] = ZZ; acc[r][3] = ZZ;
        }
        #pragma unroll
        for (int j = 0; j < 4; j++) {
            ulonglong2 u = row[2 * j];
            ulonglong2 w = row[2 * j + 1];
            #pragma unroll
            for (int r = 0; r < 4; r++) {
                acc[r][0] = f2fma(xx[r][4*j+0], u.x, acc[r][0]);
                acc[r][1] = f2fma(xx[r][4*j+1], u.y, acc[r][1]);
                acc[r][2] = f2fma(xx[r][4*j+2], w.x, acc[r][2]);
                acc[r][3] = f2fma(xx[r][4*j+3], w.y, acc[r][3]);
            }
        }
        // paced zero-fill: 2 float4 per thread per k-pair
        __stcs(&z4[(2 * p + 0) * 64 + t], zf4);
        __stcs(&z4[(2 * p + 1) * 64 + t], zf4);

        const unsigned long long c2v = c2p[p];
        #pragma unroll
        for (int r = 0; r < 4; r++) {
            unsigned long long dot  = f2add(f2add(acc[r][0], acc[r][1]),
                                            f2add(acc[r][2], acc[r][3]));
            unsigned long long dist = f2add(f2add(X2[r], c2v), dot);
            float d0, d1; upk2(dist, d0, d1);
            float cd = d0; int ck = 2 * p;
            if (d1 < d0) { cd = d1; ck = 2 * p + 1; }   // first-min semantics
            if (cd < best[r]) { best[r] = cd; bi[r] = ck; }
        }
    }

    // pack (orderable dist, global k): min over keys == first-occurrence argmin
    const size_t kb = ((size_t)sp * Dc + d) * Bc;
    #pragma unroll
    for (int r = 0; r < 4; r++) {
        g_key[kb + t + 64 * r] = ((unsigned long long)orderable(best[r]) << 32)
                               | (unsigned long long)(sp * KH + bi[r]);
    }
}

// =====================================================================
// Kernel 2 (fused finish): combine + embed + one_hot ones + EMA outputs.
// grid = Dc, block = 256 (thread = b).
// acc layout [e][Kc+1] (padded -> conflict-free banks), smem atomic scatter.
// =====================================================================
#define KP (Kc + 1)
#define K2_ACC_BYTES (Ec * KP * 4)                         // 65600
#define K2_SMEM (K2_ACC_BYTES + Kc * 4 + Kc * 4)           // + scnt + sinv = 73792

extern __shared__ unsigned char smemE[];

__global__ void __launch_bounds__(256)
vq_finish(const float* __restrict__ cw_q,
          const float* __restrict__ codebook,
          const float* __restrict__ ema,
          float* __restrict__ out)
{
    float* acc  = (float*)smemE;                            // [Ec][KP]
    int*   scnt = (int*)(smemE + K2_ACC_BYTES);             // [Kc]
    float* sinv = (float*)(smemE + K2_ACC_BYTES + Kc * 4);  // [Kc]

    const int d = blockIdx.x;
    const int t = threadIdx.x;
    const int b = t;

    // combine split keys -> argmin index (coalesced loads)
    unsigned long long key = g_key[((size_t)0 * Dc + d) * Bc + b];
    #pragma unroll
    for (int sp = 1; sp < KSPLIT; sp++) {
        unsigned long long k2 = g_key[((size_t)sp * Dc + d) * Bc + b];
        if (k2 < key) key = k2;
    }
    const int idx = (int)(key & 0xFFFFFFFFull);

    // zero acc + scnt
    #pragma unroll
    for (int i = t; i < Ec * KP; i += 256) acc[i] = 0.f;
    #pragma unroll
    for (int i = t; i < Kc; i += 256) scnt[i] = 0;
    __syncthreads();

    atomicAdd(&scnt[idx], 1);

    // scatter x into acc (random idx -> spread banks)
    {
        const float4* xp = (const float4*)(cw_q + ((size_t)b * Dc + d) * Ec);
        #pragma unroll
        for (int q = 0; q < 4; q++) {
            float4 v = xp[q];
            atomicAdd(&acc[(4*q+0) * KP + idx], v.x);
            atomicAdd(&acc[(4*q+1) * KP + idx], v.y);
            atomicAdd(&acc[(4*q+2) * KP + idx], v.z);
            atomicAdd(&acc[(4*q+3) * KP + idx], v.w);
        }
    }

    // one_hot: the single 1.0 for (b, d) (slab pre-zeroed by K1)
    out[OFF_OH + (size_t)b * (Dc * Kc) + (size_t)d * Kc + idx] = 1.0f;

    // cw_embed[b, d*16..] = codebook[d][idx] (64B gather, L2-hot)
    {
        const float4* ce = (const float4*)(codebook + ((size_t)d * Kc + idx) * Ec);
        float4 v0 = __ldg(ce + 0);
        float4 v1 = __ldg(ce + 1);
        float4 v2 = __ldg(ce + 2);
        float4 v3 = __ldg(ce + 3);
        float4* dst = (float4*)(out + OFF_EMB + (size_t)b * (Dc * Ec) + (size_t)d * Ec);
        dst[0] = v0; dst[1] = v1; dst[2] = v2; dst[3] = v3;
    }
    __syncthreads();

    // per-k: new_ema_counts + hoisted reciprocal (4 divides per thread)
    const float* emad = ema + (size_t)d * Kc;
    #pragma unroll
    for (int k = t; k < Kc; k += 256) {
        float emak = emad[k];
        out[OFF_NEC + (size_t)d * Kc + k] = 0.999f * emak + 0.001f * (float)scnt[k];
        sinv[k] = 1.0f / (emak + 1e-6f);
    }
    __syncthreads();

    // new_codebook: fully coalesced read/modify/write
    {
        const float* cbd = codebook + (size_t)d * (Kc * Ec);
        float* ncb = out + OFF_NCB + (size_t)d * (Kc * Ec);
        #pragma unroll 4
        for (int j = 0; j < (Kc * Ec) / 256; j++) {
            int i = t + 256 * j;
            int k = i >> 4;
            int e = i & 15;
            ncb[i] = 0.999f * cbd[i] + 0.001f * (acc[e * KP + k] * sinv[k]);
        }
    }
}

extern "C" void kernel_launch(void* const* d_in, const int* in_sizes, int n_in,
                              void* d_out, int out_size)
{
    const float* cw_q     = (const float*)d_in[0];
    const float* codebook = (const float*)d_in[1];
    const float* ema      = (const float*)d_in[2];
    float* out            = (float*)d_out;

    cudaFuncSetAttribute(vq_finish, cudaFuncAttributeMaxDynamicSharedMemorySize, K2_SMEM);

    vq_argmin_zf<<<dim3(Dc, KSPLIT), 64>>>(cw_q, codebook, out);
    vq_finish<<<Dc, 256, K2_SMEM>>>(cw_q, codebook, ema, out);
}

// round 15
// speedup vs baseline: 1.1283x; 1.1283x over previous
#include <cuda_runtime.h>
#include <cstdint>
#include <cstddef>

// Problem constants
#define Bc 256
#define Dc 256
#define Kc 1024
#define Ec 16
#define KSPLIT 8
#define KH (Kc / KSPLIT)   // 128 codes per argmin block

// Output offsets (floats) within d_out, in reference return order:
// cw_embed (B, D*E), one_hot (B, D, K), new_codebook (D, K, E), new_ema (D, K)
static const size_t OFF_EMB = 0;
static const size_t OFF_OH  = (size_t)Bc * Dc * Ec;                    // 1,048,576
static const size_t OFF_NCB = OFF_OH + (size_t)Bc * Dc * Kc;           // 68,157,440
static const size_t OFF_NEC = OFF_NCB + (size_t)Dc * Kc * Ec;          // 72,351,744

// One_hot zero-fill: 67,108,864 floats / 2048 blocks = 32768 floats per block.
#define ZCHUNK 32768

// Scratch
__device__ unsigned long long g_key[KSPLIT * Dc * Bc];  // packed argmin keys
__device__ int g_sidx_db[Dc * Bc];                      // argmin, [d][b]
__device__ int g_sidx_bd[Bc * Dc];                      // argmin, [b][d]

// ---- packed f32x2 helpers (Blackwell) ----
__device__ __forceinline__ unsigned long long pk2(float a, float b) {
    unsigned long long r;
    asm("mov.b64 %0,{%1,%2};" : "=l"(r) : "f"(a), "f"(b));
    return r;
}
__device__ __forceinline__ void upk2(unsigned long long v, float& a, float& b) {
    asm("mov.b64 {%0,%1},%2;" : "=f"(a), "=f"(b) : "l"(v));
}
__device__ __forceinline__ unsigned long long f2fma(unsigned long long a, unsigned long long b, unsigned long long c) {
    unsigned long long d;
    asm("fma.rn.f32x2 %0,%1,%2,%3;" : "=l"(d) : "l"(a), "l"(b), "l"(c));
    return d;
}
__device__ __forceinline__ unsigned long long f2add(unsigned long long a, unsigned long long b) {
    unsigned long long d;
    asm("add.rn.f32x2 %0,%1,%2;" : "=l"(d) : "l"(a), "l"(b));
    return d;
}

// Map float to an order-preserving uint (no NaNs expected).
__device__ __forceinline__ unsigned int orderable(float f) {
    unsigned int u = __float_as_uint(f);
    return (u & 0x80000000u) ? ~u : (u | 0x80000000u);
}

// =====================================================================
// Kernel 1: argmin over one K-chunk + one_hot zero-fill.
// grid = (Dc, KSPLIT), block = 64. Thread t handles batches t+64r, r=0..3.
// Zero stores paced: 2 STG.128 per k-pair iteration (smooth DRAM issue).
// =====================================================================
__global__ void __launch_bounds__(64, 4)
vq_argmin_zf(const float* __restrict__ cw_q,
             const float* __restrict__ codebook,
             float* __restrict__ out)
{
    // cpack[(k>>1)*32 + e*2 + (k&1)] = codebook[d][sp*KH + k][e]
    __shared__ float cpack[KH * Ec];         // 8 KB
    __shared__ float c2f[KH];                // 0.5 KB (code pairs adjacent)

    const int d  = blockIdx.x;
    const int sp = blockIdx.y;
    const int t  = threadIdx.x;
    const float* cb = codebook + ((size_t)d * Kc + (size_t)sp * KH) * Ec;

    // stage + pack codebook chunk (512 float4s, 8 per thread)
    #pragma unroll
    for (int i = t; i < (KH * Ec) / 4; i += 64) {
        float4 v = ((const float4*)cb)[i];
        int k  = i >> 2;
        int e0 = (i & 3) * 4;
        float* dstp = &cpack[(k >> 1) * 32 + (k & 1)];
        dstp[(e0 + 0) * 2] = v.x;
        dstp[(e0 + 1) * 2] = v.y;
        dstp[(e0 + 2) * 2] = v.z;
        dstp[(e0 + 3) * 2] = v.w;
    }
    __syncthreads();

    // per-k squared norms (2 per thread)
    #pragma unroll
    for (int k = t; k < KH; k += 64) {
        const float* cp = cpack + (k >> 1) * 32 + (k & 1);
        float s = 0.f;
        #pragma unroll
        for (int e = 0; e < 16; e++) { float c = cp[e * 2]; s += c * c; }
        c2f[k] = s;
    }
    __syncthreads();

    // load x for 4 batches; pack (-2x) duplicates (exactly -2 * original chain)
    unsigned long long xx[4][16];
    unsigned long long X2[4];
    #pragma unroll
    for (int r = 0; r < 4; r++) {
        const float* xp = cw_q + (size_t)(t + 64 * r) * (Dc * Ec) + (size_t)d * Ec;
        float x2 = 0.f;
        #pragma unroll
        for (int q = 0; q < 4; q++) {
            float4 v = ((const float4*)xp)[q];
            x2 += v.x * v.x; x2 += v.y * v.y; x2 += v.z * v.z; x2 += v.w * v.w;
            xx[r][4*q+0] = pk2(-2.0f*v.x, -2.0f*v.x);
            xx[r][4*q+1] = pk2(-2.0f*v.y, -2.0f*v.y);
            xx[r][4*q+2] = pk2(-2.0f*v.z, -2.0f*v.z);
            xx[r][4*q+3] = pk2(-2.0f*v.w, -2.0f*v.w);
        }
        X2[r] = pk2(x2, x2);
    }

    const unsigned long long ZZ = pk2(0.0f, 0.0f);
    const unsigned long long* c2p = (const unsigned long long*)c2f;
    const ulonglong2* cp2 = (const ulonglong2*)cpack;

    float best[4] = {3.4e38f, 3.4e38f, 3.4e38f, 3.4e38f};
    int   bi[4]   = {0, 0, 0, 0};

    float4* z4 = (float4*)(out + OFF_OH + (size_t)(d * KSPLIT + sp) * ZCHUNK);
    const float4 zf4 = make_float4(0.f, 0.f, 0.f, 0.f);

    // 64 k-pairs; 2 paced zero-stores per pair = 128 float4/thread total
    #pragma unroll 1
    for (int p = 0; p < KH / 2; p++) {
        const ulonglong2* row = cp2 + p * 8;
        unsigned long long acc[4][4];
        #pragma unroll
        for (int r = 0; r < 4; r++) {
            acc[r][0] = ZZ; acc[r][1] = ZZ; acc[r][2] = ZZ; acc[r][3] = ZZ;
        }
        #pragma unroll
        for (int j = 0; j < 4; j++) {
            ulonglong2 u = row[2 * j];
            ulonglong2 w = row[2 * j + 1];
            #pragma unroll
            for (int r = 0; r < 4; r++) {
                acc[r][0] = f2fma(xx[r][4*j+0], u.x, acc[r][0]);
                acc[r][1] = f2fma(xx[r][4*j+1], u.y, acc[r][1]);
                acc[r][2] = f2fma(xx[r][4*j+2], w.x, acc[r][2]);
                acc[r][3] = f2fma(xx[r][4*j+3], w.y, acc[r][3]);
            }
        }
        // paced zero-fill: 2 float4 per thread per k-pair
        __stcs(&z4[(2 * p + 0) * 64 + t], zf4);
        __stcs(&z4[(2 * p + 1) * 64 + t], zf4);

        const unsigned long long c2v = c2p[p];
        #pragma unroll
        for (int r = 0; r < 4; r++) {
            unsigned long long dot  = f2add(f2add(acc[r][0], acc[r][1]),
                                            f2add(acc[r][2], acc[r][3]));
            unsigned long long dist = f2add(f2add(X2[r], c2v), dot);
            float d0, d1; upk2(dist, d0, d1);
            float cd = d0; int ck = 2 * p;
            if (d1 < d0) { cd = d1; ck = 2 * p + 1; }   // first-min semantics
            if (cd < best[r]) { best[r] = cd; bi[r] = ck; }
        }
    }

    // pack (orderable dist, global k): min over keys == first-occurrence argmin
    const size_t kb = ((size_t)sp * Dc + d) * Bc;
    #pragma unroll
    for (int r = 0; r < 4; r++) {
        g_key[kb + t + 64 * r] = ((unsigned long long)orderable(best[r]) << 32)
                               | (unsigned long long)(sp * KH + bi[r]);
    }
}

// =====================================================================
// Kernel 2a: combine split keys -> sidx in both layouts.
// grid = Dc, block = 256 (thread = b). All key loads coalesced.
// =====================================================================
__global__ void __launch_bounds__(256)
vq_combine()
{
    const int d = blockIdx.x;
    const int b = threadIdx.x;

    unsigned long long key = g_key[((size_t)0 * Dc + d) * Bc + b];
    #pragma unroll
    for (int sp = 1; sp < KSPLIT; sp++) {
        unsigned long long k2 = g_key[((size_t)sp * Dc + d) * Bc + b];
        if (k2 < key) key = k2;
    }
    const int idx = (int)(key & 0xFFFFFFFFull);
    g_sidx_db[(size_t)d * Bc + b] = idx;   // coalesced
    g_sidx_bd[(size_t)b * Dc + d] = idx;   // L2 write-merged across blocks
}

// =====================================================================
// Kernel 2b: cw_embed + one_hot scatter. grid = Bc, block = 256 (thread = d).
// =====================================================================
__global__ void __launch_bounds__(256)
vq_embed_oh(const float* __restrict__ codebook,
            float* __restrict__ out)
{
    const int b = blockIdx.x;
    const int d = threadIdx.x;

    const int idx = g_sidx_bd[(size_t)b * Dc + d];   // coalesced

    // one_hot: the single 1.0 for (b, d) (slab pre-zeroed by K1)
    out[OFF_OH + (size_t)b * (Dc * Kc) + (size_t)d * Kc + idx] = 1.0f;

    // cw_embed[b, d*16..]: gather codebook[d][idx] (L2-resident), coalesced store
    const float4* ce = (const float4*)(codebook + ((size_t)d * Kc + idx) * Ec);
    float4 v0 = __ldg(ce + 0);
    float4 v1 = __ldg(ce + 1);
    float4 v2 = __ldg(ce + 2);
    float4 v3 = __ldg(ce + 3);
    float4* dst = (float4*)(out + OFF_EMB + (size_t)b * (Dc * Ec) + (size_t)d * Ec);
    dst[0] = v0; dst[1] = v1; dst[2] = v2; dst[3] = v3;
}

// =====================================================================
// Kernel 3: EMA outputs via smem atomic scatter. grid = Dc, block = 512.
// Threads 0-255 own the scatter (thread = b); all 512 share zero-fill,
// nec/sinv, and the ncb stream. acc layout [e][Kc+1] (conflict-free).
// =====================================================================
#define KP (Kc + 1)
#define K3_ACC_BYTES (Ec * KP * 4)                         // 65600
#define K3_SMEM (K3_ACC_BYTES + Kc * 4 + Kc * 4)           // + scnt + sinv = 73792
#define K3_THREADS 512

extern __shared__ unsigned char smemE[];

__global__ void __launch_bounds__(K3_THREADS)
vq_ema(const float* __restrict__ cw_q,
       const float* __restrict__ codebook,
       const float* __restrict__ ema,
       float* __restrict__ out)
{
    float* acc  = (float*)smemE;                            // [Ec][KP]
    int*   scnt = (int*)(smemE + K3_ACC_BYTES);             // [Kc]
    float* sinv = (float*)(smemE + K3_ACC_BYTES + Kc * 4);  // [Kc]

    const int d = blockIdx.x;
    const int t = threadIdx.x;

    // scatter owners load their idx early (overlaps the zero-fill)
    int idx = 0;
    if (t < Bc) idx = g_sidx_db[(size_t)d * Bc + t];   // coalesced

    // zero acc + scnt (all 512 threads)
    #pragma unroll
    for (int i = t; i < Ec * KP; i += K3_THREADS) acc[i] = 0.f;
    #pragma unroll
    for (int i = t; i < Kc; i += K3_THREADS) scnt[i] = 0;
    __syncthreads();

    // histogram + scatter x (threads 0-255; thread = b)
    if (t < Bc) {
        atomicAdd(&scnt[idx], 1);
        const float4* xp = (const float4*)(cw_q + ((size_t)t * Dc + d) * Ec);
        #pragma unroll
        for (int q = 0; q < 4; q++) {
            float4 v = xp[q];
            atomicAdd(&acc[(4*q+0) * KP + idx], v.x);
            atomicAdd(&acc[(4*q+1) * KP + idx], v.y);
            atomicAdd(&acc[(4*q+2) * KP + idx], v.z);
            atomicAdd(&acc[(4*q+3) * KP + idx], v.w);
        }
    }
    __syncthreads();

    // per-k: new_ema_counts + hoisted reciprocal (2 divides per thread)
    const float* emad = ema + (size_t)d * Kc;
    #pragma unroll
    for (int k = t; k < Kc; k += K3_THREADS) {
        float emak = emad[k];
        out[OFF_NEC + (size_t)d * Kc + k] = 0.999f * emak + 0.001f * (float)scnt[k];
        sinv[k] = 1.0f / (emak + 1e-6f);
    }
    __syncthreads();

    // new_codebook: fully coalesced read/modify/write (32 iters/thread)
    {
        const float* cbd = codebook + (size_t)d * (Kc * Ec);
        float* ncb = out + OFF_NCB + (size_t)d * (Kc * Ec);
        #pragma unroll 4
        for (int j = 0; j < (Kc * Ec) / K3_THREADS; j++) {
            int i = t + K3_THREADS * j;
            int k = i >> 4;
            int e = i & 15;
            ncb[i] = 0.999f * cbd[i] + 0.001f * (acc[e * KP + k] * sinv[k]);
        }
    }
}

extern "C" void kernel_launch(void* const* d_in, const int* in_sizes, int n_in,
                              void* d_out, int out_size)
{
    const float* cw_q     = (const float*)d_in[0];
    const float* codebook = (const float*)d_in[1];
    const float* ema      = (const float*)d_in[2];
    float* out            = (float*)d_out;

    cudaFuncSetAttribute(vq_ema, cudaFuncAttributeMaxDynamicSharedMemorySize, K3_SMEM);

    vq_argmin_zf<<<dim3(Dc, KSPLIT), 64>>>(cw_q, codebook, out);
    vq_combine<<<Dc, 256>>>();
    vq_embed_oh<<<Bc, 256>>>(codebook, out);
    vq_ema<<<Dc, K3_THREADS, K3_SMEM>>>(cw_q, codebook, ema, out);
}